// round 5
// baseline (speedup 1.0000x reference)
#include <cuda_runtime.h>
#include <cuda_bf16.h>
#include <cstdint>

#define EPS_F      1e-8f
#define EPS4_F     4e-8f          // 4*EPS (clip on raw squares)
#define EPS16_F    1.6e-7f        // 16*EPS (clip on z product of raw squares)
#define EPS64_F    6.4e-7f        // 64*EPS (clip on raw det product)
#define TAU4_INV   13.333333333333334f  // 4 / 0.3  (cube-root 1/64 factor folded in)
#define LOG2E_F    1.4426950408889634f

static constexpr int NT  = 256;
static constexpr int NB1 = 1024;
static constexpr int BPT = 2;                       // boxes per thread
static constexpr int TILE_BOXES = NT * BPT;         // 512
static constexpr int TILE_F  = TILE_BOXES * 7;      // 3584 floats per array
static constexpr int TILE_F4 = TILE_F / 4;          // 896 float4 per array

__device__ float2       g_partials[NB1];
__device__ unsigned int g_done_count;

__device__ __forceinline__ float warp_sum(float v) {
    #pragma unroll
    for (int off = 16; off > 0; off >>= 1)
        v += __shfl_xor_sync(0xFFFFFFFFu, v, off);
    return v;
}
__device__ __forceinline__ float fsqrt_ap(float x) {
    float r; asm("sqrt.approx.f32 %0, %1;" : "=f"(r) : "f"(x)); return r;
}
__device__ __forceinline__ float ex2_ap(float x) {
    float r; asm("ex2.approx.f32 %0, %1;" : "=f"(r) : "f"(x)); return r;
}
__device__ __forceinline__ float lg2_ap(float x) {
    float r; asm("lg2.approx.f32 %0, %1;" : "=f"(r) : "f"(x)); return r;
}

// per-box loss; factor 0.25 on covariances folded out algebraically
__device__ __forceinline__ void box_loss(
    const float* __restrict__ p, const float* __restrict__ g,
    float& lsum, float& msum)
{
    float p0 = p[0], p1 = p[1], p2 = p[2], p3 = p[3], p4v = p[4], p5 = p[5], p6 = p[6];
    float g0 = g[0], g1 = g[1], g2 = g[2], g3 = g[3], g4v = g[4], g5 = g[5], g6 = g[6];

    float dx = p0 - g0, dy = p1 - g1, dz = p2 - g2;
    float mu = fmaf(dx, dx, fmaf(dy, dy, dz * dz));

    // raw squared extents (covariance eigvals are these * 0.25)
    float tp = p3 * p3, up = p4v * p4v, vp = p5 * p5;
    float tt = g3 * g3, ut = g4v * g4v, vt = g5 * g5;

    // sigma_p eigenvalue clip (EPS on 0.25*sq -> 4*EPS on sq)
    float mtp = fmaxf(tp, EPS4_F);
    float mup = fmaxf(up, EPS4_F);
    float mvp = fmaxf(vp, EPS4_F);

    // 2x2 xy block of M (in raw units)
    float cd = __cosf(p6 - g6);
    float cc = cd * cd;
    float ss = 1.0f - cc;
    float t1 = mtp * tt, t2 = mup * ut;     // aligned products
    float t3 = mtp * ut, t4 = mup * tt;     // crossed products
    float trM = fmaf(cc, t1 + t2, ss * (t3 + t4));
    // sqrt(l1)+sqrt(l2) = sqrt(trM + 2*sqrt(detM)), detM = t1*t2
    float trS = fsqrt_ap(fmaf(2.0f, fsqrt_ap(t1 * t2), trM));

    // z block (raw units): clip EPS on 0.0625*prod -> 16*EPS on prod
    float sz = fsqrt_ap(fmaxf(mvp * vt, EPS16_F));

    float traces = (tp + up + vp) + (tt + ut + vt);
    float w2 = fmaf(0.25f, traces - 2.0f * (trS + sz), mu);

    // det(sigma_t) = raw/64; clip EPS -> 64*EPS on raw; (raw/64)^(-1/3) = 4*raw^(-1/3)
    float detr = fmaxf(tt * ut * vt, EPS64_F);
    float invd = ex2_ap(lg2_ap(detr) * (-1.0f / 3.0f)) * TAU4_INV;

    float loss = 1.0f - ex2_ap(-w2 * invd * LOG2E_F);
    if (g0 != 0.0f) { lsum += loss; msum += 1.0f; }
}

__global__ __launch_bounds__(NT, 4) void gwd_fused(
    const float* __restrict__ pred,
    const float* __restrict__ gt,
    float* __restrict__ out,
    int total)
{
    __shared__ float sp[TILE_F];
    __shared__ float sg[TILE_F];

    const int ntiles = (total + TILE_BOXES - 1) / TILE_BOXES;
    const long long total_f = (long long)total * 7;

    float lsum = 0.0f;
    float msum = 0.0f;

    for (int tile = blockIdx.x; tile < ntiles; tile += gridDim.x) {
        const long long base = (long long)tile * TILE_F;

        if (total_f - base >= TILE_F) {
            // batched: all loads issued before any store (max MLP)
            const float4* __restrict__ p4 = (const float4*)(pred + base);
            const float4* __restrict__ g4 = (const float4*)(gt   + base);
            const int t = threadIdx.x;
            float4 rp0 = p4[t], rp1 = p4[t + 256], rp2 = p4[t + 512];
            float4 rg0 = g4[t], rg1 = g4[t + 256], rg2 = g4[t + 512];
            float4 rp3, rg3;
            const bool half = (t < TILE_F4 - 768);   // 128 remaining
            if (half) { rp3 = p4[t + 768]; rg3 = g4[t + 768]; }
            float4* sp4 = (float4*)sp;
            float4* sg4 = (float4*)sg;
            sp4[t] = rp0; sp4[t + 256] = rp1; sp4[t + 512] = rp2;
            sg4[t] = rg0; sg4[t + 256] = rg1; sg4[t + 512] = rg2;
            if (half) { sp4[t + 768] = rp3; sg4[t + 768] = rg3; }
        } else {
            const int remain = (int)(total_f - base);
            for (int i = threadIdx.x; i < remain; i += NT) {
                sp[i] = pred[base + i];
                sg[i] = gt[base + i];
            }
        }
        __syncthreads();

        const int b0 = tile * TILE_BOXES + threadIdx.x;
        const int b1 = b0 + NT;
        // stride-7 smem access: gcd(7,32)=1 -> conflict-free
        if (b1 < total) {
            box_loss(sp + 7 * threadIdx.x,            sg + 7 * threadIdx.x,            lsum, msum);
            box_loss(sp + 7 * threadIdx.x + 7 * NT,   sg + 7 * threadIdx.x + 7 * NT,   lsum, msum);
        } else {
            if (b0 < total)
                box_loss(sp + 7 * threadIdx.x, sg + 7 * threadIdx.x, lsum, msum);
        }
        __syncthreads();
    }

    // block reduction
    lsum = warp_sum(lsum);
    msum = warp_sum(msum);

    __shared__ float sl[NT / 32];
    __shared__ float sm[NT / 32];
    int lane = threadIdx.x & 31;
    int wid  = threadIdx.x >> 5;
    if (lane == 0) { sl[wid] = lsum; sm[wid] = msum; }
    __syncthreads();

    __shared__ bool is_last;
    if (threadIdx.x == 0) {
        float vl = 0.0f, vm = 0.0f;
        #pragma unroll
        for (int w = 0; w < NT / 32; w++) { vl += sl[w]; vm += sm[w]; }
        g_partials[blockIdx.x] = make_float2(vl, vm);
        __threadfence();
        unsigned int ticket = atomicAdd(&g_done_count, 1u);
        is_last = (ticket == (unsigned)(gridDim.x - 1));
    }
    __syncthreads();

    if (is_last) {
        double l = 0.0, m = 0.0;
        for (int i = threadIdx.x; i < NB1; i += NT) {
            float2 v = g_partials[i];
            l += (double)v.x;
            m += (double)v.y;
        }
        #pragma unroll
        for (int off = 16; off > 0; off >>= 1) {
            l += __shfl_xor_sync(0xFFFFFFFFu, l, off);
            m += __shfl_xor_sync(0xFFFFFFFFu, m, off);
        }
        __shared__ double dl[NT / 32];
        __shared__ double dm[NT / 32];
        if (lane == 0) { dl[wid] = l; dm[wid] = m; }
        __syncthreads();
        if (threadIdx.x == 0) {
            double vl = 0.0, vm = 0.0;
            #pragma unroll
            for (int w = 0; w < NT / 32; w++) { vl += dl[w]; vm += dm[w]; }
            out[0] = (float)(vl / (vm + (double)EPS_F));
            g_done_count = 0;   // reset for next graph replay
        }
    }
}

extern "C" void kernel_launch(void* const* d_in, const int* in_sizes, int n_in,
                              void* d_out, int out_size)
{
    const float* pred = (const float*)d_in[0];
    const float* gt   = (const float*)d_in[1];
    float* out = (float*)d_out;

    int total = in_sizes[0] / 7;

    gwd_fused<<<NB1, NT>>>(pred, gt, out, total);
}